// round 11
// baseline (speedup 1.0000x reference)
#include <cuda_runtime.h>
#include <cstdint>

// ---------------- problem constants ----------------
#define B_  8
#define T_  64
#define D_  256
#define H_  1024
#define CPB 8            // CTAs per batch (cluster size)
#define SLICE 128        // H rows per CTA
#define NT  512
#define LR    1e-3f
#define DECAY 0.02f
#define MU    0.9f
#define EPS_  1e-6f

#define CLUSTER_ARRIVE() asm volatile("barrier.cluster.arrive.aligned;" ::: "memory")
#define CLUSTER_WAIT()   asm volatile("barrier.cluster.wait.aligned;"  ::: "memory")

// ---------------- device scratch ----------------
__device__ float g_XN[B_*T_*D_];
__device__ float g_GRAM[B_*T_*T_];
__device__ float g_P1[B_*T_*H_];
// transposed exchange: g_RED1T[b][k][src], rows of 8 floats (32B) -> reduce = 2x LDG.128
__device__ float g_RED1T[B_][324][CPB];

__device__ __forceinline__ uint32_t mapa_rank(uint32_t laddr, int rank)
{
    uint32_t ra;
    asm volatile("mapa.shared::cluster.u32 %0, %1, %2;" : "=r"(ra) : "r"(laddr), "r"(rank));
    return ra;
}
__device__ __forceinline__ void stsc(uint32_t ra, float v)
{
    asm volatile("st.shared::cluster.b32 [%0], %1;" :: "r"(ra), "r"(__float_as_uint(v)) : "memory");
}

// ---------------- precompute: normalize keys ----------------
__global__ void k_norm(const float* __restrict__ keys)
{
    int bt = blockIdx.x, tid = threadIdx.x;
    float v = keys[bt*D_ + tid];
    float ss = v*v;
    #pragma unroll
    for (int o=16;o;o>>=1) ss += __shfl_xor_sync(~0u, ss, o);
    __shared__ float ws[8];
    __shared__ float s_scale;
    if ((tid&31)==0) ws[tid>>5] = ss;
    __syncthreads();
    if (tid==0) {
        float tot=0.f;
        #pragma unroll
        for (int i=0;i<8;i++) tot += ws[i];
        s_scale = 1.0f / fmaxf(sqrtf(tot), 1e-12f);
    }
    __syncthreads();
    g_XN[bt*D_ + tid] = v * s_scale;
}

// ---------------- precompute: Gram matrix ----------------
__global__ void k_gram()
{
    int bt = blockIdx.x, b = bt / T_, t = bt % T_;
    int tid = threadIdx.x, lane = tid&31, w = tid>>5;
    __shared__ float xt[D_];
    xt[tid] = g_XN[bt*D_ + tid];
    __syncthreads();
    for (int r = w; r < T_; r += 8) {
        const float* xr = &g_XN[(b*T_+r)*D_];
        float acc = 0.f;
        #pragma unroll
        for (int k=lane; k<D_; k+=32) acc += xr[k]*xt[k];
        #pragma unroll
        for (int o=16;o;o>>=1) acc += __shfl_xor_sync(~0u, acc, o);
        if (lane==0) g_GRAM[(b*T_+t)*T_ + r] = acc;
    }
}

// ---------------- precompute: P1 = w1_0 @ xn ----------------
__global__ void k_p1(const float* __restrict__ w1)
{
    int hc = blockIdx.x;   // 32 chunks of 32 H-rows
    int b  = blockIdx.y;
    int tid = threadIdx.x, lane = tid&31, w = tid>>5;
    __shared__ float xns[32][D_];
    for (int half = 0; half < 2; half++) {
        for (int idx = tid; idx < 32*D_; idx += 256) {
            int tt = idx / D_, d = idx % D_;
            xns[tt][d] = g_XN[(b*T_ + half*32 + tt)*D_ + d];
        }
        __syncthreads();
        for (int j = 0; j < 4; j++) {
            int h = hc*32 + w*4 + j;
            float wr[8];
            #pragma unroll
            for (int k=0;k<8;k++) wr[k] = w1[h*D_ + lane + 32*k];
            for (int tt = 0; tt < 32; tt++) {
                float acc = 0.f;
                #pragma unroll
                for (int k=0;k<8;k++) acc += wr[k]*xns[tt][lane + 32*k];
                #pragma unroll
                for (int o=16;o;o>>=1) acc += __shfl_xor_sync(~0u, acc, o);
                if (lane==0) g_P1[(b*T_ + half*32 + tt)*H_ + h] = acc;
            }
        }
        __syncthreads();
    }
}

// ---------------- main kernel ----------------
__global__ __launch_bounds__(NT, 1) __cluster_dims__(CPB, 1, 1)
void k_main(const float* __restrict__ values, const float* __restrict__ w2,
            float* __restrict__ out_preds, float* __restrict__ out_surp)
{
    extern __shared__ float sm[];
    float* B2s  = sm;                        // [64][132] h history
    float* A1f  = B2s  + 64*132;             // [64][132] dh' history
    float* A2f  = A1f  + 64*132;             // [64][264] dpred history
    float* fxr  = A2f  + 64*264;             // [16][132] backward-dot warp partials
    float* zp   = fxr  + 16*132;             // [1024] combine scratch
    float* h_s  = zp   + 1024;               // [128]
    float* gp_s = h_s  + 128;                // [128]
    float* dp_s = gp_s + 128;                // [256]
    float* red_s= dp_s + 256;                // [324]
    float* cf2  = red_s+ 324;                // [64]
    float* cfu  = cf2  + 64;                 // [64]
    float* cf_s = cfu  + 64;                 // [64]
    float* Pc   = cf_s + 64;                 // [64]
    float* Mc   = Pc   + 64;                 // [64]
    float* gr_s = Mc   + 64;                 // [68] next Gram row
    float* rs   = gr_s + 68;                 // [8] hn2 partials (4 used)
    float* rs2  = rs   + 8;                  // [8] dn2 partials
    float* rs3  = rs2  + 8;                  // [8] gn2 partials (4 used)
    float* gred = rs3  + 8;                  // [8] per-CTA gn2 (DSMEM)
    float* sc   = gred + 8;                  // 0=alpha 5=cf_t

    const int tid = threadIdx.x, lane = tid&31, wid = tid>>5;
    const int ti = tid & 15, td = tid >> 4;
    const int b     = blockIdx.x / CPB;
    const int crank = blockIdx.x % CPB;
    const int base  = crank * SLICE;

    // ---- register-resident w2 tile ----
    float w2r[8][8];
    {
        const float* wbase = w2 + base + ti*8;
        #pragma unroll
        for (int jd=0;jd<8;jd++) {
            const float4* p = (const float4*)(wbase + (td*8+jd)*(size_t)H_);
            float4 x = p[0], y = p[1];
            w2r[jd][0]=x.x; w2r[jd][1]=x.y; w2r[jd][2]=x.z; w2r[jd][3]=x.w;
            w2r[jd][4]=y.x; w2r[jd][5]=y.y; w2r[jd][6]=y.z; w2r[jd][7]=y.w;
        }
    }
    if (tid < T_) { Pc[tid] = 0.f; Mc[tid] = 0.f; }
    if (tid==0) sc[0] = 1.0f;
    // zero A2f/B2s so speculative (rr >= t) reads in the unrolled dots are benign
    for (int i = tid; i < 64*264; i += NT) A2f[i] = 0.f;
    for (int i = tid; i < 64*132; i += NT) B2s[i] = 0.f;
    __syncthreads();

    // ---- pre-loop: h_0 = gelu(P1_0) ----
    if (tid < SLICE) {
        float z = g_P1[(b*T_)*H_ + base + tid];
        float ph = 0.5f*(1.0f + erff(z*0.70710678118654752f));
        float h  = z*ph;
        float gp = ph + z*0.39894228040143268f*__expf(-0.5f*z*z);
        h_s[tid] = h; gp_s[tid] = gp; B2s[tid] = h;
        float hh2 = h*h;
        #pragma unroll
        for (int o=16;o;o>>=1) hh2 += __shfl_xor_sync(~0u, hh2, o);
        if (lane==0) rs[wid] = hh2;
    }
    float vv  = (tid < D_) ? values[(b*T_)*D_ + tid] : 0.f;
    __syncthreads();

    for (int t = 0; t < T_; t++) {
        const float alpha = sc[0];

        // ---- (A) pred partials (register GEMV) -> transposed L2 exchange ----
        {
            float4 hv0 = *(const float4*)&h_s[ti*8];
            float4 hv1 = *(const float4*)&h_s[ti*8+4];
            float hb[8] = {hv0.x,hv0.y,hv0.z,hv0.w,hv1.x,hv1.y,hv1.z,hv1.w};
            float p[8] = {0,0,0,0,0,0,0,0};
            #pragma unroll
            for (int jd=0;jd<8;jd++)
                #pragma unroll
                for (int ii=0;ii<8;ii++) p[jd] += w2r[jd][ii]*hb[ii];
            #pragma unroll
            for (int jd=0;jd<8;jd++) {
                p[jd] += __shfl_xor_sync(~0u, p[jd], 1);
                p[jd] += __shfl_xor_sync(~0u, p[jd], 2);
                p[jd] += __shfl_xor_sync(~0u, p[jd], 4);
                p[jd] += __shfl_xor_sync(~0u, p[jd], 8);
            }
            if ((lane&15)==0) {
                #pragma unroll
                for (int jd=0;jd<8;jd++)
                    g_RED1T[b][td*8+jd][crank] = p[jd];
            }
        }
        // v_r dots: 4 ranks per warp, unrolled ILP, jointly-pipelined reduction
        {
            float4 hv = *(const float4*)&h_s[lane*4];
            float acc[4];
            #pragma unroll
            for (int j=0;j<4;j++) {
                int rr = wid + j*16;
                float4 bv = *(const float4*)&B2s[rr*132 + lane*4];
                acc[j] = bv.x*hv.x + bv.y*hv.y + bv.z*hv.z + bv.w*hv.w;
            }
            #pragma unroll
            for (int o=16;o;o>>=1) {
                #pragma unroll
                for (int j=0;j<4;j++) acc[j] += __shfl_xor_sync(~0u, acc[j], o);
            }
            if (lane==0) {
                #pragma unroll
                for (int j=0;j<4;j++) {
                    int rr = wid + j*16;
                    if (rr < t) g_RED1T[b][256+rr][crank] = acc[j];
                }
            }
        }
        // hn2 partial
        if (wid==0) {
            float v = (lane<4) ? rs[lane] : 0.f;
            v += __shfl_xor_sync(~0u, v, 1);
            v += __shfl_xor_sync(~0u, v, 2);
            v += __shfl_xor_sync(~0u, v, 4);
            if (lane==0) g_RED1T[b][320][crank] = v;
        }
        CLUSTER_ARRIVE();

        // ---- (B) next-step prefetch (overlaps barrier wait) ----
        float p1n = 0.f, vn = 0.f;
        if (t+1 < T_) {
            if (tid <= t+1)  gr_s[tid] = g_GRAM[(b*T_+t+1)*T_ + tid];
            if (tid < SLICE) p1n = g_P1[(b*T_+t+1)*H_ + base + tid];
            if (tid < D_)    vn  = values[(b*T_+t+1)*D_ + tid];
        }
        CLUSTER_WAIT();

        // ---- (C) reduce partials: 2x LDG.128 per thread ----
        if (tid < 321) {
            const float4* g4 = (const float4*)&g_RED1T[b][tid][0];
            float4 a = g4[0], c = g4[1];
            float s = (a.x+a.y)+(a.z+a.w)+(c.x+c.y)+(c.z+c.w);
            red_s[tid] = s;
            if (tid >= 256 && tid < 320) cf2[tid-256] = Pc[tid-256]*s;
        }
        __syncthreads();

        // ---- (D) pred rank part: 4 rank-groups x 128 float2 columns ----
        {
            int g = tid >> 7, dc = tid & 127;
            float2 acc2 = make_float2(0.f, 0.f);
            if (g==0) {
                float2 rv = *(const float2*)&red_s[2*dc];
                acc2.x = alpha*rv.x; acc2.y = alpha*rv.y;
            }
            for (int r=g; r<t; r+=4) {
                float c = cf2[r];
                float2 av = *(const float2*)&A2f[r*264 + 2*dc];
                acc2.x += c*av.x; acc2.y += c*av.y;
            }
            *(float2*)&zp[g*256 + 2*dc] = acc2;
        }
        __syncthreads();
        if (tid < D_) {
            float pr = zp[tid] + zp[256+tid] + zp[512+tid] + zp[768+tid];
            float dp = 2.0f*(pr - vv);
            dp_s[tid] = dp;
            A2f[t*264 + tid] = dp;
            if (crank==0) out_preds[(b*T_+t)*D_ + tid] = pr;
            float dn2p = dp*dp;
            #pragma unroll
            for (int o=16;o;o>>=1) dn2p += __shfl_xor_sync(~0u, dn2p, o);
            if (lane==0) rs2[wid] = dn2p;
        }
        __syncthreads();

        // ---- (E) u[r]: 4 ranks per warp unrolled + backward register GEMV ----
        {
            const float4* dp4 = (const float4*)dp_s;
            float4 d0 = dp4[lane], d1 = dp4[32+lane];
            float acc[4];
            #pragma unroll
            for (int j=0;j<4;j++) {
                int rr = wid + j*16;
                const float4* row = (const float4*)(A2f + rr*264);
                float4 a0 = row[lane], a1 = row[32+lane];
                acc[j] = a0.x*d0.x + a0.y*d0.y + a0.z*d0.z + a0.w*d0.w
                       + a1.x*d1.x + a1.y*d1.y + a1.z*d1.z + a1.w*d1.w;
            }
            #pragma unroll
            for (int o=16;o;o>>=1) {
                #pragma unroll
                for (int j=0;j<4;j++) acc[j] += __shfl_xor_sync(~0u, acc[j], o);
            }
            if (lane==0) {
                #pragma unroll
                for (int j=0;j<4;j++) {
                    int rr = wid + j*16;
                    if (rr < t) cfu[rr] = Pc[rr]*acc[j];
                }
            }
        }
        {
            float4 dv0 = *(const float4*)&dp_s[td*8];
            float4 dv1 = *(const float4*)&dp_s[td*8+4];
            float db[8] = {dv0.x,dv0.y,dv0.z,dv0.w,dv1.x,dv1.y,dv1.z,dv1.w};
            float f[8] = {0,0,0,0,0,0,0,0};
            #pragma unroll
            for (int jd=0;jd<8;jd++)
                #pragma unroll
                for (int ji=0;ji<8;ji++) f[ji] += w2r[jd][ji]*db[jd];
            #pragma unroll
            for (int ji=0;ji<8;ji++) f[ji] += __shfl_xor_sync(~0u, f[ji], 16);
            if (lane < 16) {
                *(float4*)&fxr[wid*132 + ti*8]   = make_float4(f[0],f[1],f[2],f[3]);
                *(float4*)&fxr[wid*132 + ti*8+4] = make_float4(f[4],f[5],f[6],f[7]);
            }
        }
        __syncthreads();

        // ---- (F-combine) 4-way over warp partials + rank loop ----
        {
            int q = tid >> 7, i = tid & 127;
            float s = fxr[(q*4+0)*132+i] + fxr[(q*4+1)*132+i]
                    + fxr[(q*4+2)*132+i] + fxr[(q*4+3)*132+i];
            float acc = alpha * s;
            for (int r=q; r<t; r+=4) acc += cfu[r]*B2s[r*132+i];
            zp[q*128 + i] = acc;
        }
        __syncthreads();

        // ---- (F-final) dh', A1f[t], gn2 ----
        if (tid < SLICE) {
            float dh  = zp[tid] + zp[128+tid] + zp[256+tid] + zp[384+tid];
            float dhp = dh * gp_s[tid];
            A1f[t*132 + tid] = dhp;
            float gn2 = dhp*dhp;
            #pragma unroll
            for (int o=16;o;o>>=1) gn2 += __shfl_xor_sync(~0u, gn2, o);
            if (lane==0) rs3[wid] = gn2;
        }
        __syncthreads();

        // ---- (G) DSMEM gn2 push (8 scalars); clip-free coefficient updates ----
        if (wid==0) {
            float v = (lane<4) ? rs3[lane] : 0.f;
            v += __shfl_xor_sync(~0u, v, 1);
            v += __shfl_xor_sync(~0u, v, 2);
            v += __shfl_xor_sync(~0u, v, 4);
            if (lane < CPB) {
                uint32_t la = (uint32_t)__cvta_generic_to_shared(&gred[crank]);
                stsc(mapa_rank(la, lane), v);
            }
        }
        if (tid < t) {
            float m = Mc[tid]*MU;
            Mc[tid] = m;
            float p = Pc[tid]*(1.0f - DECAY) - LR*m;
            Pc[tid] = p;
            cf_s[tid] = p * gr_s[tid];
        }
        if (tid==0) sc[0] = alpha*(1.0f - DECAY);
        __syncthreads();
        CLUSTER_ARRIVE();

        // ---- (H) partial next-z (ranks r<t) overlapped with barrier wait ----
        {
            int g = tid >> 7, i = tid & 127;
            float z = (g==0) ? (alpha*(1.0f-DECAY))*p1n : 0.f;
            for (int r=g; r<t; r+=4) z += cf_s[r]*A1f[r*132 + i];
            zp[g*128 + i] = z;
        }
        CLUSTER_WAIT();

        // ---- (I) gnorm, clip, rank-t coefficients ----
        if (wid==0) {
            float a = (lane<CPB) ? gred[lane] : 0.f;
            float c = (lane<8)   ? rs2[lane]  : 0.f;
            #pragma unroll
            for (int o=16;o;o>>=1) { a += __shfl_xor_sync(~0u, a, o);
                                     c += __shfl_xor_sync(~0u, c, o); }
            if (lane==0) {
                float gn = sqrtf(a + c*red_s[320]);   // G[t][t] == 1
                float clip = fminf(1.0f/(gn + EPS_), 1.0f);
                if (crank==0) out_surp[b*T_ + t] = gn;
                float p = -LR*clip;
                Mc[t] = clip; Pc[t] = p;
                sc[5] = (t+1<T_) ? p*gr_s[t] : 0.f;
            }
        }
        __syncthreads();

        // ---- (K) finish next h: add rank-t term, GELU ----
        if (t+1 < T_ && tid < SLICE) {
            float z = zp[tid] + zp[128+tid] + zp[256+tid] + zp[384+tid]
                    + sc[5]*A1f[t*132 + tid];
            float ph = 0.5f*(1.0f + erff(z*0.70710678118654752f));
            float h  = z*ph;
            float gp = ph + z*0.39894228040143268f*__expf(-0.5f*z*z);
            h_s[tid] = h; gp_s[tid] = gp;
            B2s[(t+1)*132 + tid] = h;
            float hh2 = h*h;
            #pragma unroll
            for (int o=16;o;o>>=1) hh2 += __shfl_xor_sync(~0u, hh2, o);
            if (lane==0) rs[wid] = hh2;
        }
        vv = vn;
        __syncthreads();
    }
}

// ---------------- launch ----------------
extern "C" void kernel_launch(void* const* d_in, const int* in_sizes, int n_in,
                              void* d_out, int out_size)
{
    (void)in_sizes; (void)n_in; (void)out_size;
    const float* keys   = (const float*)d_in[0];
    const float* values = (const float*)d_in[1];
    const float* w1     = (const float*)d_in[2];
    const float* w2     = (const float*)d_in[3];
    float* out       = (float*)d_out;
    float* out_preds = out;                 // [B,T,D]
    float* out_surp  = out + B_*T_*D_;      // [B,T]

    k_norm<<<B_*T_, D_>>>(keys);
    k_gram<<<B_*T_, 256>>>();
    dim3 gp1(H_/32, B_);
    k_p1<<<gp1, 256>>>(w1);

    const size_t f32_cnt =
        (size_t)64*132 + 64*132 + 64*264 + 16*132 + 1024
        + 128 + 128 + 256 + 324 + 64*5 + 68 + 8*5;
    const size_t smem_bytes = f32_cnt * sizeof(float);
    cudaFuncSetAttribute(k_main, cudaFuncAttributeMaxDynamicSharedMemorySize,
                         (int)smem_bytes);
    k_main<<<B_*CPB, NT, smem_bytes>>>(values, w2, out_preds, out_surp);
}

// round 12
// speedup vs baseline: 1.0370x; 1.0370x over previous
#include <cuda_runtime.h>
#include <cstdint>

// ---------------- problem constants ----------------
#define B_  8
#define T_  64
#define D_  256
#define H_  1024
#define CPB 8            // CTAs per batch (cluster size)
#define SLICE 128        // H rows per CTA
#define NT  512
#define LR    1e-3f
#define DECAY 0.02f
#define MU    0.9f
#define EPS_  1e-6f

#define CLUSTER_ARRIVE() asm volatile("barrier.cluster.arrive.aligned;" ::: "memory")
#define CLUSTER_WAIT()   asm volatile("barrier.cluster.wait.aligned;"  ::: "memory")

// ---------------- device scratch ----------------
__device__ float g_XN[B_*T_*D_];
__device__ float g_GRAM[B_*T_*T_];
__device__ float g_P1[B_*T_*H_];
// transposed exchange: g_RED1T[b][k][src], rows of 8 floats (32B) -> reduce = 2x LDG.128
__device__ float g_RED1T[B_][324][CPB];

__device__ __forceinline__ uint32_t mapa_rank(uint32_t laddr, int rank)
{
    uint32_t ra;
    asm volatile("mapa.shared::cluster.u32 %0, %1, %2;" : "=r"(ra) : "r"(laddr), "r"(rank));
    return ra;
}
__device__ __forceinline__ void stsc(uint32_t ra, float v)
{
    asm volatile("st.shared::cluster.b32 [%0], %1;" :: "r"(ra), "r"(__float_as_uint(v)) : "memory");
}

// ---------------- precompute: normalize keys ----------------
__global__ void k_norm(const float* __restrict__ keys)
{
    int bt = blockIdx.x, tid = threadIdx.x;
    float v = keys[bt*D_ + tid];
    float ss = v*v;
    #pragma unroll
    for (int o=16;o;o>>=1) ss += __shfl_xor_sync(~0u, ss, o);
    __shared__ float ws[8];
    __shared__ float s_scale;
    if ((tid&31)==0) ws[tid>>5] = ss;
    __syncthreads();
    if (tid==0) {
        float tot=0.f;
        #pragma unroll
        for (int i=0;i<8;i++) tot += ws[i];
        s_scale = 1.0f / fmaxf(sqrtf(tot), 1e-12f);
    }
    __syncthreads();
    g_XN[bt*D_ + tid] = v * s_scale;
}

// ---------------- precompute: Gram matrix ----------------
__global__ void k_gram()
{
    int bt = blockIdx.x, b = bt / T_, t = bt % T_;
    int tid = threadIdx.x, lane = tid&31, w = tid>>5;
    __shared__ float xt[D_];
    xt[tid] = g_XN[bt*D_ + tid];
    __syncthreads();
    for (int r = w; r < T_; r += 8) {
        const float* xr = &g_XN[(b*T_+r)*D_];
        float acc = 0.f;
        #pragma unroll
        for (int k=lane; k<D_; k+=32) acc += xr[k]*xt[k];
        #pragma unroll
        for (int o=16;o;o>>=1) acc += __shfl_xor_sync(~0u, acc, o);
        if (lane==0) g_GRAM[(b*T_+t)*T_ + r] = acc;
    }
}

// ---------------- precompute: P1 = w1_0 @ xn ----------------
__global__ void k_p1(const float* __restrict__ w1)
{
    int hc = blockIdx.x;   // 32 chunks of 32 H-rows
    int b  = blockIdx.y;
    int tid = threadIdx.x, lane = tid&31, w = tid>>5;
    __shared__ float xns[32][D_];
    for (int half = 0; half < 2; half++) {
        for (int idx = tid; idx < 32*D_; idx += 256) {
            int tt = idx / D_, d = idx % D_;
            xns[tt][d] = g_XN[(b*T_ + half*32 + tt)*D_ + d];
        }
        __syncthreads();
        for (int j = 0; j < 4; j++) {
            int h = hc*32 + w*4 + j;
            float wr[8];
            #pragma unroll
            for (int k=0;k<8;k++) wr[k] = w1[h*D_ + lane + 32*k];
            for (int tt = 0; tt < 32; tt++) {
                float acc = 0.f;
                #pragma unroll
                for (int k=0;k<8;k++) acc += wr[k]*xns[tt][lane + 32*k];
                #pragma unroll
                for (int o=16;o;o>>=1) acc += __shfl_xor_sync(~0u, acc, o);
                if (lane==0) g_P1[(b*T_ + half*32 + tt)*H_ + h] = acc;
            }
        }
        __syncthreads();
    }
}

// ---------------- main kernel ----------------
__global__ __launch_bounds__(NT, 1) __cluster_dims__(CPB, 1, 1)
void k_main(const float* __restrict__ values, const float* __restrict__ w2,
            float* __restrict__ out_preds, float* __restrict__ out_surp)
{
    extern __shared__ float sm[];
    float* B2s  = sm;                        // [64][132] h history
    float* A1f  = B2s  + 64*132;             // [64][132] dh' history
    float* A2f  = A1f  + 64*132;             // [64][264] dpred history
    float* fxr  = A2f  + 64*264;             // [16][132] backward-dot warp partials
    float* zp   = fxr  + 16*132;             // [1024] combine scratch
    float* h_s  = zp   + 1024;               // [128]
    float* gp_s = h_s  + 128;                // [128]
    float* dp_s = gp_s + 128;                // [256]
    float* red_s= dp_s + 256;                // [324]
    float* cf2  = red_s+ 324;                // [64]
    float* cfu  = cf2  + 64;                 // [64]
    float* cf_s = cfu  + 64;                 // [64]
    float* Pc   = cf_s + 64;                 // [64]
    float* Mc   = Pc   + 64;                 // [64]
    float* gr_s = Mc   + 64;                 // [68] next Gram row
    float* rs   = gr_s + 68;                 // [8] hn2 partials (4 used)
    float* rs2  = rs   + 8;                  // [8] dn2 partials
    float* gred2= rs2  + 8;                  // [32] gn2 per (srcCTA, warp) via DSMEM
    float* sc   = gred2+ 32;                 // 0=alpha

    const int tid = threadIdx.x, lane = tid&31, wid = tid>>5;
    const int ti = tid & 15, td = tid >> 4;
    const int b     = blockIdx.x / CPB;
    const int crank = blockIdx.x % CPB;
    const int base  = crank * SLICE;

    // ---- register-resident w2 tile ----
    float w2r[8][8];
    {
        const float* wbase = w2 + base + ti*8;
        #pragma unroll
        for (int jd=0;jd<8;jd++) {
            const float4* p = (const float4*)(wbase + (td*8+jd)*(size_t)H_);
            float4 x = p[0], y = p[1];
            w2r[jd][0]=x.x; w2r[jd][1]=x.y; w2r[jd][2]=x.z; w2r[jd][3]=x.w;
            w2r[jd][4]=y.x; w2r[jd][5]=y.y; w2r[jd][6]=y.z; w2r[jd][7]=y.w;
        }
    }
    if (tid < T_) { Pc[tid] = 0.f; Mc[tid] = 0.f; }
    if (tid==0) sc[0] = 1.0f;

    // ---- pre-loop: h_0 = gelu(P1_0) ----
    __syncthreads();
    if (tid < SLICE) {
        float z = g_P1[(b*T_)*H_ + base + tid];
        float ph = 0.5f*(1.0f + erff(z*0.70710678118654752f));
        float h  = z*ph;
        float gp = ph + z*0.39894228040143268f*__expf(-0.5f*z*z);
        h_s[tid] = h; gp_s[tid] = gp; B2s[tid] = h;
        float hh2 = h*h;
        #pragma unroll
        for (int o=16;o;o>>=1) hh2 += __shfl_xor_sync(~0u, hh2, o);
        if (lane==0) rs[wid] = hh2;
    }
    float vv  = (tid < D_) ? values[(b*T_)*D_ + tid] : 0.f;
    __syncthreads();

    for (int t = 0; t < T_; t++) {
        const float alpha = sc[0];

        // ---- (A) pred partials (register GEMV) -> transposed L2 exchange ----
        {
            float4 hv0 = *(const float4*)&h_s[ti*8];
            float4 hv1 = *(const float4*)&h_s[ti*8+4];
            float hb[8] = {hv0.x,hv0.y,hv0.z,hv0.w,hv1.x,hv1.y,hv1.z,hv1.w};
            float p[8] = {0,0,0,0,0,0,0,0};
            #pragma unroll
            for (int jd=0;jd<8;jd++)
                #pragma unroll
                for (int ii=0;ii<8;ii++) p[jd] += w2r[jd][ii]*hb[ii];
            #pragma unroll
            for (int jd=0;jd<8;jd++) {
                p[jd] += __shfl_xor_sync(~0u, p[jd], 1);
                p[jd] += __shfl_xor_sync(~0u, p[jd], 2);
                p[jd] += __shfl_xor_sync(~0u, p[jd], 4);
                p[jd] += __shfl_xor_sync(~0u, p[jd], 8);
            }
            if ((lane&15)==0) {
                #pragma unroll
                for (int jd=0;jd<8;jd++)
                    g_RED1T[b][td*8+jd][crank] = p[jd];
            }
        }
        // v_r dots: warp-per-rank, lane-contiguous (conflict-free)
        for (int rr = wid; rr < t; rr += 16) {
            float4 bv = *(const float4*)&B2s[rr*132 + lane*4];
            float4 hv = *(const float4*)&h_s[lane*4];
            float acc = bv.x*hv.x + bv.y*hv.y + bv.z*hv.z + bv.w*hv.w;
            #pragma unroll
            for (int o=16;o;o>>=1) acc += __shfl_xor_sync(~0u, acc, o);
            if (lane==0) g_RED1T[b][256+rr][crank] = acc;
        }
        // hn2 partial
        if (wid==0) {
            float v = (lane<4) ? rs[lane] : 0.f;
            v += __shfl_xor_sync(~0u, v, 1);
            v += __shfl_xor_sync(~0u, v, 2);
            v += __shfl_xor_sync(~0u, v, 4);
            if (lane==0) g_RED1T[b][320][crank] = v;
        }
        CLUSTER_ARRIVE();

        // ---- (B) next-step prefetch (overlaps barrier wait) ----
        float p1n = 0.f, vn = 0.f;
        if (t+1 < T_) {
            if (tid <= t+1)  gr_s[tid] = g_GRAM[(b*T_+t+1)*T_ + tid];
            if (tid < SLICE) p1n = g_P1[(b*T_+t+1)*H_ + base + tid];
            if (tid < D_)    vn  = values[(b*T_+t+1)*D_ + tid];
        }
        CLUSTER_WAIT();

        // ---- (C) reduce partials: 2x LDG.128 per thread ----
        if (tid < 321) {
            const float4* g4 = (const float4*)&g_RED1T[b][tid][0];
            float4 a = g4[0], c = g4[1];
            float s = (a.x+a.y)+(a.z+a.w)+(c.x+c.y)+(c.z+c.w);
            red_s[tid] = s;
            if (tid >= 256 && tid < 320) cf2[tid-256] = Pc[tid-256]*s;
        }
        __syncthreads();

        // ---- (D) pred rank part: 4 rank-groups x 128 float2 columns ----
        {
            int g = tid >> 7, dc = tid & 127;
            float2 acc2 = make_float2(0.f, 0.f);
            if (g==0) {
                float2 rv = *(const float2*)&red_s[2*dc];
                acc2.x = alpha*rv.x; acc2.y = alpha*rv.y;
            }
            for (int r=g; r<t; r+=4) {
                float c = cf2[r];
                float2 av = *(const float2*)&A2f[r*264 + 2*dc];
                acc2.x += c*av.x; acc2.y += c*av.y;
            }
            *(float2*)&zp[g*256 + 2*dc] = acc2;
        }
        __syncthreads();
        if (tid < D_) {
            float pr = zp[tid] + zp[256+tid] + zp[512+tid] + zp[768+tid];
            float dp = 2.0f*(pr - vv);
            dp_s[tid] = dp;
            A2f[t*264 + tid] = dp;
            if (crank==0) out_preds[(b*T_+t)*D_ + tid] = pr;
            float dn2p = dp*dp;
            #pragma unroll
            for (int o=16;o;o>>=1) dn2p += __shfl_xor_sync(~0u, dn2p, o);
            if (lane==0) rs2[wid] = dn2p;
        }
        __syncthreads();

        // ---- (E) u[r] warp-per-rank (conflict-free) + backward register GEMV ----
        for (int rr = wid; rr < t; rr += 16) {
            const float4* row = (const float4*)(A2f + rr*264);
            const float4* dp4 = (const float4*)dp_s;
            float4 a0 = row[lane], a1 = row[32+lane];
            float4 d0 = dp4[lane], d1 = dp4[32+lane];
            float acc = a0.x*d0.x + a0.y*d0.y + a0.z*d0.z + a0.w*d0.w
                      + a1.x*d1.x + a1.y*d1.y + a1.z*d1.z + a1.w*d1.w;
            #pragma unroll
            for (int o=16;o;o>>=1) acc += __shfl_xor_sync(~0u, acc, o);
            if (lane==0) cfu[rr] = Pc[rr]*acc;
        }
        {
            float4 dv0 = *(const float4*)&dp_s[td*8];
            float4 dv1 = *(const float4*)&dp_s[td*8+4];
            float db[8] = {dv0.x,dv0.y,dv0.z,dv0.w,dv1.x,dv1.y,dv1.z,dv1.w};
            float f[8] = {0,0,0,0,0,0,0,0};
            #pragma unroll
            for (int jd=0;jd<8;jd++)
                #pragma unroll
                for (int ji=0;ji<8;ji++) f[ji] += w2r[jd][ji]*db[jd];
            #pragma unroll
            for (int ji=0;ji<8;ji++) f[ji] += __shfl_xor_sync(~0u, f[ji], 16);
            if (lane < 16) {
                *(float4*)&fxr[wid*132 + ti*8]   = make_float4(f[0],f[1],f[2],f[3]);
                *(float4*)&fxr[wid*132 + ti*8+4] = make_float4(f[4],f[5],f[6],f[7]);
            }
        }
        __syncthreads();

        // ---- (F-combine) 4-way over warp partials + rank loop ----
        {
            int q = tid >> 7, i = tid & 127;
            float s = fxr[(q*4+0)*132+i] + fxr[(q*4+1)*132+i]
                    + fxr[(q*4+2)*132+i] + fxr[(q*4+3)*132+i];
            float acc = alpha * s;
            for (int r=q; r<t; r+=4) acc += cfu[r]*B2s[r*132+i];
            zp[q*128 + i] = acc;
        }
        __syncthreads();

        // ---- (F-final merged with G) ----
        // warps 0-3: dh', A1f[t], per-warp gn2 -> direct DSMEM push (32 slots)
        // warps 4-5: Mc/Pc/cf_s recurrences; thread 192: alpha update
        if (tid < SLICE) {
            float dh  = zp[tid] + zp[128+tid] + zp[256+tid] + zp[384+tid];
            float dhp = dh * gp_s[tid];
            A1f[t*132 + tid] = dhp;
            float gn2 = dhp*dhp;
            #pragma unroll
            for (int o=16;o;o>>=1) gn2 += __shfl_xor_sync(~0u, gn2, o);
            if (lane < CPB) {
                uint32_t la = (uint32_t)__cvta_generic_to_shared(&gred2[crank*4 + wid]);
                stsc(mapa_rank(la, lane), gn2);
            }
        } else if (tid >= 128 && tid < 192) {
            int r = tid - 128;
            if (r < t) {
                float m = Mc[r]*MU;
                Mc[r] = m;
                float p = Pc[r]*(1.0f - DECAY) - LR*m;
                Pc[r] = p;
                cf_s[r] = p * gr_s[r];
            }
        } else if (tid == 192) {
            sc[0] = alpha*(1.0f - DECAY);
        }
        __syncthreads();
        CLUSTER_ARRIVE();

        // ---- (H) partial next-z (ranks r<t) overlapped with barrier wait ----
        {
            int g = tid >> 7, i = tid & 127;
            float z = (g==0) ? (alpha*(1.0f-DECAY))*p1n : 0.f;
            for (int r=g; r<t; r+=4) z += cf_s[r]*A1f[r*132 + i];
            zp[g*128 + i] = z;
        }
        CLUSTER_WAIT();

        // ---- (I) gnorm/clip: every warp reduces redundantly (no broadcast sync) ----
        float cft;
        {
            float a = gred2[lane];                      // 32 (srcCTA, warp) partials
            float c = (lane<8) ? rs2[lane] : 0.f;
            #pragma unroll
            for (int o=16;o;o>>=1) { a += __shfl_xor_sync(~0u, a, o);
                                     c += __shfl_xor_sync(~0u, c, o); }
            float gn = sqrtf(a + c*red_s[320]);         // G[t][t] == 1
            float clip = fminf(1.0f/(gn + EPS_), 1.0f);
            float pt = -LR*clip;
            if (tid==0) {
                Mc[t] = clip; Pc[t] = pt;
                if (crank==0) out_surp[b*T_ + t] = gn;
            }
            cft = (t+1<T_) ? pt*gr_s[t] : 0.f;
        }

        // ---- (K) finish next h: add rank-t term, GELU (no intervening sync) ----
        if (t+1 < T_ && tid < SLICE) {
            float z = zp[tid] + zp[128+tid] + zp[256+tid] + zp[384+tid]
                    + cft*A1f[t*132 + tid];
            float ph = 0.5f*(1.0f + erff(z*0.70710678118654752f));
            float h  = z*ph;
            float gp = ph + z*0.39894228040143268f*__expf(-0.5f*z*z);
            h_s[tid] = h; gp_s[tid] = gp;
            B2s[(t+1)*132 + tid] = h;
            float hh2 = h*h;
            #pragma unroll
            for (int o=16;o;o>>=1) hh2 += __shfl_xor_sync(~0u, hh2, o);
            if (lane==0) rs[wid] = hh2;
        }
        vv = vn;
        __syncthreads();
    }
}

// ---------------- launch ----------------
extern "C" void kernel_launch(void* const* d_in, const int* in_sizes, int n_in,
                              void* d_out, int out_size)
{
    (void)in_sizes; (void)n_in; (void)out_size;
    const float* keys   = (const float*)d_in[0];
    const float* values = (const float*)d_in[1];
    const float* w1     = (const float*)d_in[2];
    const float* w2     = (const float*)d_in[3];
    float* out       = (float*)d_out;
    float* out_preds = out;                 // [B,T,D]
    float* out_surp  = out + B_*T_*D_;      // [B,T]

    k_norm<<<B_*T_, D_>>>(keys);
    k_gram<<<B_*T_, 256>>>();
    dim3 gp1(H_/32, B_);
    k_p1<<<gp1, 256>>>(w1);

    const size_t f32_cnt =
        (size_t)64*132 + 64*132 + 64*264 + 16*132 + 1024
        + 128 + 128 + 256 + 324 + 64*5 + 68 + 8 + 8 + 32 + 8;
    const size_t smem_bytes = f32_cnt * sizeof(float);
    cudaFuncSetAttribute(k_main, cudaFuncAttributeMaxDynamicSharedMemorySize,
                         (int)smem_bytes);
    k_main<<<B_*CPB, NT, smem_bytes>>>(values, w2, out_preds, out_surp);
}